// round 11
// baseline (speedup 1.0000x reference)
#include <cuda_runtime.h>
#include <cstdint>

#define SGRID 14
#define BATCH 4096
#define NCELLS (BATCH * SGRID * SGRID)   // 802816
#define THREADS 128
#define CPW 32                           // cells per warp
#define CPB (CPW * (THREADS / 32))       // 128 cells per block
#define NBLOCKS (NCELLS / CPB)           // 6272
#define F4_PER_TENSOR_W (CPW * 30 / 4)   // 240 float4 per tensor per warp

__global__ void init_out_kernel(float* out) {
    if (threadIdx.x == 0) out[0] = 0.0f;
}

__device__ __forceinline__ void cp_async16(uint32_t smem_addr, const void* gptr) {
    asm volatile("cp.async.cg.shared.global [%0], [%1], 16;\n"
                 :: "r"(smem_addr), "l"(gptr) : "memory");
}

__global__ void __launch_bounds__(THREADS)
yolo_loss_kernel(const float* __restrict__ pred,
                 const float* __restrict__ targ,
                 float* __restrict__ out)
{
    // per-warp private tiles: [warp][pred 960 | targ 960] floats
    __shared__ float sbuf[(THREADS / 32) * 2 * CPW * 30];

    const int tid  = threadIdx.x;
    const int wid  = tid >> 5;
    const int lane = tid & 31;

    float* wbuf = sbuf + wid * (2 * CPW * 30);
    const uint32_t wsm = (uint32_t)__cvta_generic_to_shared(wbuf);

    // this warp's 32 cells start here (contiguous 960 floats per tensor)
    const size_t cell0 = (size_t)blockIdx.x * CPB + (size_t)wid * CPW;
    const float4* gp = reinterpret_cast<const float4*>(pred + cell0 * 30);
    const float4* gt = reinterpret_cast<const float4*>(targ + cell0 * 30);

    // ---- warp-autonomous async stage: 15 x 16B per lane, no block barrier ----
#pragma unroll
    for (int j = 0; j < 15; j++) {
        int i = lane + j * 32;                    // 0 .. 479
        const void* src = (i < F4_PER_TENSOR_W) ? (const void*)(gp + i)
                                                : (const void*)(gt + (i - F4_PER_TENSOR_W));
        cp_async16(wsm + (uint32_t)i * 16u, src);
    }
    asm volatile("cp.async.commit_group;\n" ::: "memory");
    asm volatile("cp.async.wait_group 0;\n" ::: "memory");
    __syncwarp();   // all lanes' waits done => all warp copies visible

    const float* p = wbuf + lane * 30;
    const float* t = wbuf + CPW * 30 + lane * 30;

    float loss;
    bool obj = (t[4] > 0.0f);   // target conf is exactly 0.0 or 1.0

    if (obj) {
        // ---- class loss: sum_{c=10..29} (p-t)^2 ----
        float cls = 0.0f;
#pragma unroll
        for (int c = 10; c < 30; c++) {
            float d = p[c] - t[c];
            cls = fmaf(d, d, cls);
        }

        // ---- IoU of both pred boxes vs target box 0 ----
        const float invS = 1.0f / (float)SGRID;
        float tcx = t[0] * invS, tcy = t[1] * invS;
        float t1x = tcx - t[2] * 0.5f, t2x = tcx + t[2] * 0.5f;
        float t1y = tcy - t[3] * 0.5f, t2y = tcy + t[3] * 0.5f;
        float area_t = (t2x - t1x) * (t2y - t1y);

        float iou0, iou1;
#pragma unroll
        for (int b = 0; b < 2; b++) {
            float bx = (b == 0) ? p[0] : p[5];
            float by = (b == 0) ? p[1] : p[6];
            float bw = (b == 0) ? p[2] : p[7];
            float bh = (b == 0) ? p[3] : p[8];
            float cx = bx * invS, cy = by * invS;
            float p1x = cx - bw * 0.5f, p2x = cx + bw * 0.5f;
            float p1y = cy - bh * 0.5f, p2y = cy + bh * 0.5f;
            float ltx = fmaxf(p1x, t1x), lty = fmaxf(p1y, t1y);
            float rbx = fminf(p2x, t2x), rby = fminf(p2y, t2y);
            float wx = fmaxf(rbx - ltx, 0.0f);
            float wy = fmaxf(rby - lty, 0.0f);
            float inter = wx * wy;
            float area_p = (p2x - p1x) * (p2y - p1y);
            float iou = inter / (area_p + area_t - inter);
            if (b == 0) iou0 = iou; else iou1 = iou;
        }

        bool pick1 = (iou0 <= iou1);
        float iou_best = pick1 ? iou1 : iou0;

        float psx = pick1 ? p[5] : p[0];
        float psy = pick1 ? p[6] : p[1];
        float psw = pick1 ? p[7] : p[2];
        float psh = pick1 ? p[8] : p[3];
        float psc = pick1 ? p[9] : p[4];
        float tsx = pick1 ? t[5] : t[0];
        float tsy = pick1 ? t[6] : t[1];
        float tsw = pick1 ? t[7] : t[2];
        float tsh = pick1 ? t[8] : t[3];

        float dx = psx - tsx, dy = psy - tsy;
        float dw = sqrtf(psw) - sqrtf(tsw);
        float dh = sqrtf(psh) - sqrtf(tsh);
        float reg = dx*dx + dy*dy + dw*dw + dh*dh;

        float dc = psc - iou_best;

        loss = cls + 5.0f * reg + dc * dc;
    } else {
        // ---- no-object loss on both confidences ----
        float d4 = p[4] - t[4];
        float d9 = p[9] - t[9];
        loss = 0.5f * (d4 * d4 + d9 * d9);
    }

    // ---- warp shfl reduce -> one returnless atomic per warp ----
#pragma unroll
    for (int o = 16; o > 0; o >>= 1)
        loss += __shfl_xor_sync(0xffffffffu, loss, o);

    if (lane == 0)
        atomicAdd(out, loss * (1.0f / (float)BATCH));   // unused return -> REDG
}

extern "C" void kernel_launch(void* const* d_in, const int* in_sizes, int n_in,
                              void* d_out, int out_size)
{
    const float* pred = (const float*)d_in[0];
    const float* targ = (const float*)d_in[1];
    float* out = (float*)d_out;
    (void)in_sizes; (void)n_in; (void)out_size;

    init_out_kernel<<<1, 32>>>(out);
    yolo_loss_kernel<<<NBLOCKS, THREADS>>>(pred, targ, out);
}

// round 12
// speedup vs baseline: 1.6207x; 1.6207x over previous
#include <cuda_runtime.h>
#include <cstdint>

#define SGRID 14
#define BATCH 4096
#define NCELLS (BATCH * SGRID * SGRID)   // 802816
#define THREADS 128
#define CPB 128                          // cells per block
#define NBLOCKS (NCELLS / CPB)           // 6272
#define F4_PER_TENSOR (CPB * 30 / 4)     // 960

__device__ float g_parts[NBLOCKS];       // per-block partial sums (rewritten every replay)

__device__ __forceinline__ void cp_async16(uint32_t smem_addr, const void* gptr) {
    asm volatile("cp.async.cg.shared.global [%0], [%1], 16;\n"
                 :: "r"(smem_addr), "l"(gptr) : "memory");
}

__global__ void __launch_bounds__(THREADS)
yolo_loss_kernel(const float* __restrict__ pred,
                 const float* __restrict__ targ)
{
    __shared__ float sbuf[2 * CPB * 30];   // pred tile then targ tile (30720 B)
    __shared__ float warp_sums[THREADS / 32];

    const size_t base = (size_t)blockIdx.x * (CPB * 30);
    const float4* gp = reinterpret_cast<const float4*>(pred + base);
    const float4* gt = reinterpret_cast<const float4*>(targ + base);
    const uint32_t sbase = (uint32_t)__cvta_generic_to_shared(sbuf);
    const int tid = threadIdx.x;

    // ---- async coalesced stage: 15 x 16B per thread ----
#pragma unroll
    for (int j = 0; j < 15; j++) {
        int i = tid + j * THREADS;               // 0 .. 1919
        const void* src = (i < F4_PER_TENSOR) ? (const void*)(gp + i)
                                              : (const void*)(gt + (i - F4_PER_TENSOR));
        cp_async16(sbase + (uint32_t)i * 16u, src);
    }
    asm volatile("cp.async.commit_group;\n" ::: "memory");
    asm volatile("cp.async.wait_group 0;\n" ::: "memory");
    __syncthreads();

    const float* p = sbuf + tid * 30;
    const float* t = sbuf + CPB * 30 + tid * 30;

    float loss;
    bool obj = (t[4] > 0.0f);   // target conf is exactly 0.0 or 1.0

    if (obj) {
        // ---- class loss: sum_{c=10..29} (p-t)^2 ----
        float cls = 0.0f;
#pragma unroll
        for (int c = 10; c < 30; c++) {
            float d = p[c] - t[c];
            cls = fmaf(d, d, cls);
        }

        // ---- IoU of both pred boxes vs target box 0 ----
        const float invS = 1.0f / (float)SGRID;
        float tcx = t[0] * invS, tcy = t[1] * invS;
        float t1x = tcx - t[2] * 0.5f, t2x = tcx + t[2] * 0.5f;
        float t1y = tcy - t[3] * 0.5f, t2y = tcy + t[3] * 0.5f;
        float area_t = (t2x - t1x) * (t2y - t1y);

        float iou0, iou1;
#pragma unroll
        for (int b = 0; b < 2; b++) {
            float bx = (b == 0) ? p[0] : p[5];
            float by = (b == 0) ? p[1] : p[6];
            float bw = (b == 0) ? p[2] : p[7];
            float bh = (b == 0) ? p[3] : p[8];
            float cx = bx * invS, cy = by * invS;
            float p1x = cx - bw * 0.5f, p2x = cx + bw * 0.5f;
            float p1y = cy - bh * 0.5f, p2y = cy + bh * 0.5f;
            float ltx = fmaxf(p1x, t1x), lty = fmaxf(p1y, t1y);
            float rbx = fminf(p2x, t2x), rby = fminf(p2y, t2y);
            float wx = fmaxf(rbx - ltx, 0.0f);
            float wy = fmaxf(rby - lty, 0.0f);
            float inter = wx * wy;
            float area_p = (p2x - p1x) * (p2y - p1y);
            float iou = inter / (area_p + area_t - inter);
            if (b == 0) iou0 = iou; else iou1 = iou;
        }

        bool pick1 = (iou0 <= iou1);
        float iou_best = pick1 ? iou1 : iou0;

        float psx = pick1 ? p[5] : p[0];
        float psy = pick1 ? p[6] : p[1];
        float psw = pick1 ? p[7] : p[2];
        float psh = pick1 ? p[8] : p[3];
        float psc = pick1 ? p[9] : p[4];
        float tsx = pick1 ? t[5] : t[0];
        float tsy = pick1 ? t[6] : t[1];
        float tsw = pick1 ? t[7] : t[2];
        float tsh = pick1 ? t[8] : t[3];

        float dx = psx - tsx, dy = psy - tsy;
        float dw = sqrtf(psw) - sqrtf(tsw);
        float dh = sqrtf(psh) - sqrtf(tsh);
        float reg = dx*dx + dy*dy + dw*dw + dh*dh;

        float dc = psc - iou_best;

        loss = cls + 5.0f * reg + dc * dc;
    } else {
        // ---- no-object loss on both confidences ----
        float d4 = p[4] - t[4];
        float d9 = p[9] - t[9];
        loss = 0.5f * (d4 * d4 + d9 * d9);
    }

    // ---- reduction: warp shfl -> smem -> ONE plain STG per block (no atomics) ----
#pragma unroll
    for (int o = 16; o > 0; o >>= 1)
        loss += __shfl_xor_sync(0xffffffffu, loss, o);

    int wid = tid >> 5;
    int lid = tid & 31;
    if (lid == 0) warp_sums[wid] = loss;
    __syncthreads();

    if (tid == 0) {
        g_parts[blockIdx.x] =
            warp_sums[0] + warp_sums[1] + warp_sums[2] + warp_sums[3];
    }
}

__global__ void __launch_bounds__(1024)
final_reduce_kernel(float* __restrict__ out)
{
    __shared__ float warp_sums[32];
    const int tid = threadIdx.x;

    float s = 0.0f;
#pragma unroll
    for (int i = tid; i < NBLOCKS; i += 1024)
        s += g_parts[i];                 // L2-resident (just written by kernel 1)

#pragma unroll
    for (int o = 16; o > 0; o >>= 1)
        s += __shfl_xor_sync(0xffffffffu, s, o);

    int wid = tid >> 5;
    int lid = tid & 31;
    if (lid == 0) warp_sums[wid] = s;
    __syncthreads();

    if (wid == 0) {
        s = warp_sums[lid];
#pragma unroll
        for (int o = 16; o > 0; o >>= 1)
            s += __shfl_xor_sync(0xffffffffu, s, o);
        if (lid == 0)
            out[0] = s * (1.0f / (float)BATCH);
    }
}

extern "C" void kernel_launch(void* const* d_in, const int* in_sizes, int n_in,
                              void* d_out, int out_size)
{
    const float* pred = (const float*)d_in[0];
    const float* targ = (const float*)d_in[1];
    float* out = (float*)d_out;
    (void)in_sizes; (void)n_in; (void)out_size;

    yolo_loss_kernel<<<NBLOCKS, THREADS>>>(pred, targ);
    final_reduce_kernel<<<1, 1024>>>(out);
}

// round 13
// speedup vs baseline: 1.6252x; 1.0028x over previous
#include <cuda_runtime.h>
#include <cstdint>

#define SGRID 14
#define BATCH 4096
#define NCELLS (BATCH * SGRID * SGRID)   // 802816
#define THREADS 128
#define CPB 128                          // cells per block
#define NBLOCKS (NCELLS / CPB)           // 6272
#define F4_PER_TENSOR (CPB * 30 / 4)     // 960
#define FIX_SCALE 4194304.0f             // 2^22
#define NBANKS 32

__device__ unsigned long long g_bank[NBANKS];   // zeroed at load; re-zeroed by finalizer

__device__ __forceinline__ void cp_async16(uint32_t smem_addr, const void* gptr) {
    asm volatile("cp.async.cg.shared.global [%0], [%1], 16;\n"
                 :: "r"(smem_addr), "l"(gptr) : "memory");
}

__global__ void __launch_bounds__(THREADS)
yolo_loss_kernel(const float* __restrict__ pred,
                 const float* __restrict__ targ)
{
    __shared__ float sbuf[2 * CPB * 30];   // pred tile then targ tile (30720 B)
    __shared__ float warp_sums[THREADS / 32];

    const size_t base = (size_t)blockIdx.x * (CPB * 30);
    const float4* gp = reinterpret_cast<const float4*>(pred + base);
    const float4* gt = reinterpret_cast<const float4*>(targ + base);
    const uint32_t sbase = (uint32_t)__cvta_generic_to_shared(sbuf);
    const int tid = threadIdx.x;

    // ---- async coalesced stage: 15 x 16B per thread ----
#pragma unroll
    for (int j = 0; j < 15; j++) {
        int i = tid + j * THREADS;               // 0 .. 1919
        const void* src = (i < F4_PER_TENSOR) ? (const void*)(gp + i)
                                              : (const void*)(gt + (i - F4_PER_TENSOR));
        cp_async16(sbase + (uint32_t)i * 16u, src);
    }
    asm volatile("cp.async.commit_group;\n" ::: "memory");
    asm volatile("cp.async.wait_group 0;\n" ::: "memory");
    __syncthreads();

    const float* p = sbuf + tid * 30;
    const float* t = sbuf + CPB * 30 + tid * 30;

    float loss;
    bool obj = (t[4] > 0.0f);   // target conf is exactly 0.0 or 1.0

    if (obj) {
        // ---- class loss: sum_{c=10..29} (p-t)^2 ----
        float cls = 0.0f;
#pragma unroll
        for (int c = 10; c < 30; c++) {
            float d = p[c] - t[c];
            cls = fmaf(d, d, cls);
        }

        // ---- IoU of both pred boxes vs target box 0 ----
        const float invS = 1.0f / (float)SGRID;
        float tcx = t[0] * invS, tcy = t[1] * invS;
        float t1x = tcx - t[2] * 0.5f, t2x = tcx + t[2] * 0.5f;
        float t1y = tcy - t[3] * 0.5f, t2y = tcy + t[3] * 0.5f;
        float area_t = (t2x - t1x) * (t2y - t1y);

        float iou0, iou1;
#pragma unroll
        for (int b = 0; b < 2; b++) {
            float bx = (b == 0) ? p[0] : p[5];
            float by = (b == 0) ? p[1] : p[6];
            float bw = (b == 0) ? p[2] : p[7];
            float bh = (b == 0) ? p[3] : p[8];
            float cx = bx * invS, cy = by * invS;
            float p1x = cx - bw * 0.5f, p2x = cx + bw * 0.5f;
            float p1y = cy - bh * 0.5f, p2y = cy + bh * 0.5f;
            float ltx = fmaxf(p1x, t1x), lty = fmaxf(p1y, t1y);
            float rbx = fminf(p2x, t2x), rby = fminf(p2y, t2y);
            float wx = fmaxf(rbx - ltx, 0.0f);
            float wy = fmaxf(rby - lty, 0.0f);
            float inter = wx * wy;
            float area_p = (p2x - p1x) * (p2y - p1y);
            float iou = inter / (area_p + area_t - inter);
            if (b == 0) iou0 = iou; else iou1 = iou;
        }

        bool pick1 = (iou0 <= iou1);
        float iou_best = pick1 ? iou1 : iou0;

        float psx = pick1 ? p[5] : p[0];
        float psy = pick1 ? p[6] : p[1];
        float psw = pick1 ? p[7] : p[2];
        float psh = pick1 ? p[8] : p[3];
        float psc = pick1 ? p[9] : p[4];
        float tsx = pick1 ? t[5] : t[0];
        float tsy = pick1 ? t[6] : t[1];
        float tsw = pick1 ? t[7] : t[2];
        float tsh = pick1 ? t[8] : t[3];

        float dx = psx - tsx, dy = psy - tsy;
        float dw = sqrtf(psw) - sqrtf(tsw);
        float dh = sqrtf(psh) - sqrtf(tsh);
        float reg = dx*dx + dy*dy + dw*dw + dh*dh;

        float dc = psc - iou_best;

        loss = cls + 5.0f * reg + dc * dc;
    } else {
        // ---- no-object loss on both confidences ----
        float d4 = p[4] - t[4];
        float d9 = p[9] - t[9];
        loss = 0.5f * (d4 * d4 + d9 * d9);
    }

    // ---- reduction: warp shfl -> smem -> ONE returnless u64 RED per block ----
#pragma unroll
    for (int o = 16; o > 0; o >>= 1)
        loss += __shfl_xor_sync(0xffffffffu, loss, o);

    int wid = tid >> 5;
    int lid = tid & 31;
    if (lid == 0) warp_sums[wid] = loss;
    __syncthreads();

    if (tid == 0) {
        float bsum = warp_sums[0] + warp_sums[1] + warp_sums[2] + warp_sums[3];
        unsigned long long fixed =
            (unsigned long long)__float2ull_rn(bsum * FIX_SCALE);   // bsum >= 0
        unsigned long long* bank = &g_bank[blockIdx.x & (NBANKS - 1)];
        // fire-and-forget: block retires without waiting on L2 round-trip
        asm volatile("red.relaxed.gpu.global.add.u64 [%0], %1;"
                     :: "l"(bank), "l"(fixed) : "memory");
    }
}

__global__ void __launch_bounds__(32)
final_reduce_kernel(float* __restrict__ out)
{
    const int lane = threadIdx.x;
    unsigned long long v = g_bank[lane];   // kernel boundary ordered all REDs
    g_bank[lane] = 0ull;                   // self-clean for next graph replay

#pragma unroll
    for (int o = 16; o > 0; o >>= 1)
        v += __shfl_xor_sync(0xffffffffu, v, o);

    if (lane == 0)
        out[0] = (float)((double)v * (1.0 / (double)FIX_SCALE)
                         * (1.0 / (double)BATCH));
}

extern "C" void kernel_launch(void* const* d_in, const int* in_sizes, int n_in,
                              void* d_out, int out_size)
{
    const float* pred = (const float*)d_in[0];
    const float* targ = (const float*)d_in[1];
    float* out = (float*)d_out;
    (void)in_sizes; (void)n_in; (void)out_size;

    yolo_loss_kernel<<<NBLOCKS, THREADS>>>(pred, targ);
    final_reduce_kernel<<<1, 32>>>(out);
}

// round 14
// speedup vs baseline: 1.7059x; 1.0497x over previous
#include <cuda_runtime.h>
#include <cstdint>

#define SGRID 14
#define BATCH 4096
#define NCELLS (BATCH * SGRID * SGRID)   // 802816
#define THREADS 128
#define CPB 128                          // cells per block
#define NBLOCKS (NCELLS / CPB)           // 6272
#define F4_PER_TENSOR (CPB * 30 / 4)     // 960
#define FIX_SCALE 4194304.0f             // 2^22
#define SUM_MASK ((1ull << 48) - 1ull)
#define NBANKS 32

__device__ unsigned long long g_bank[NBANKS];   // zeroed at load; re-zeroed by finalizer

__device__ __forceinline__ void cp_async16(uint32_t smem_addr, const void* gptr) {
    asm volatile("cp.async.cg.shared.global [%0], [%1], 16;\n"
                 :: "r"(smem_addr), "l"(gptr) : "memory");
}

__global__ void __launch_bounds__(THREADS)
yolo_loss_kernel(const float* __restrict__ pred,
                 const float* __restrict__ targ,
                 float* __restrict__ out)
{
    __shared__ float sbuf[2 * CPB * 30];   // pred tile then targ tile (30720 B)
    __shared__ float warp_sums[THREADS / 32];

    const size_t base = (size_t)blockIdx.x * (CPB * 30);
    const float4* gp = reinterpret_cast<const float4*>(pred + base);
    const float4* gt = reinterpret_cast<const float4*>(targ + base);
    const uint32_t sbase = (uint32_t)__cvta_generic_to_shared(sbuf);
    const int tid = threadIdx.x;

    // ---- async coalesced stage: 15 x 16B per thread ----
#pragma unroll
    for (int j = 0; j < 15; j++) {
        int i = tid + j * THREADS;               // 0 .. 1919
        const void* src = (i < F4_PER_TENSOR) ? (const void*)(gp + i)
                                              : (const void*)(gt + (i - F4_PER_TENSOR));
        cp_async16(sbase + (uint32_t)i * 16u, src);
    }
    asm volatile("cp.async.commit_group;\n" ::: "memory");
    asm volatile("cp.async.wait_group 0;\n" ::: "memory");
    __syncthreads();

    const float* p = sbuf + tid * 30;
    const float* t = sbuf + CPB * 30 + tid * 30;

    float loss;
    bool obj = (t[4] > 0.0f);   // target conf is exactly 0.0 or 1.0

    if (obj) {
        // ---- class loss: sum_{c=10..29} (p-t)^2 ----
        float cls = 0.0f;
#pragma unroll
        for (int c = 10; c < 30; c++) {
            float d = p[c] - t[c];
            cls = fmaf(d, d, cls);
        }

        // ---- IoU of both pred boxes vs target box 0 ----
        const float invS = 1.0f / (float)SGRID;
        float tcx = t[0] * invS, tcy = t[1] * invS;
        float t1x = tcx - t[2] * 0.5f, t2x = tcx + t[2] * 0.5f;
        float t1y = tcy - t[3] * 0.5f, t2y = tcy + t[3] * 0.5f;
        float area_t = (t2x - t1x) * (t2y - t1y);

        float iou0, iou1;
#pragma unroll
        for (int b = 0; b < 2; b++) {
            float bx = (b == 0) ? p[0] : p[5];
            float by = (b == 0) ? p[1] : p[6];
            float bw = (b == 0) ? p[2] : p[7];
            float bh = (b == 0) ? p[3] : p[8];
            float cx = bx * invS, cy = by * invS;
            float p1x = cx - bw * 0.5f, p2x = cx + bw * 0.5f;
            float p1y = cy - bh * 0.5f, p2y = cy + bh * 0.5f;
            float ltx = fmaxf(p1x, t1x), lty = fmaxf(p1y, t1y);
            float rbx = fminf(p2x, t2x), rby = fminf(p2y, t2y);
            float wx = fmaxf(rbx - ltx, 0.0f);
            float wy = fmaxf(rby - lty, 0.0f);
            float inter = wx * wy;
            float area_p = (p2x - p1x) * (p2y - p1y);
            float iou = inter / (area_p + area_t - inter);
            if (b == 0) iou0 = iou; else iou1 = iou;
        }

        bool pick1 = (iou0 <= iou1);
        float iou_best = pick1 ? iou1 : iou0;

        float psx = pick1 ? p[5] : p[0];
        float psy = pick1 ? p[6] : p[1];
        float psw = pick1 ? p[7] : p[2];
        float psh = pick1 ? p[8] : p[3];
        float psc = pick1 ? p[9] : p[4];
        float tsx = pick1 ? t[5] : t[0];
        float tsy = pick1 ? t[6] : t[1];
        float tsw = pick1 ? t[7] : t[2];
        float tsh = pick1 ? t[8] : t[3];

        float dx = psx - tsx, dy = psy - tsy;
        float dw = sqrtf(psw) - sqrtf(tsw);
        float dh = sqrtf(psh) - sqrtf(tsh);
        float reg = dx*dx + dy*dy + dw*dw + dh*dh;

        float dc = psc - iou_best;

        loss = cls + 5.0f * reg + dc * dc;
    } else {
        // ---- no-object loss on both confidences ----
        float d4 = p[4] - t[4];
        float d9 = p[9] - t[9];
        loss = 0.5f * (d4 * d4 + d9 * d9);
    }

    // ---- reduction: warp shfl -> smem -> ONE returnless banked u64 RED ----
#pragma unroll
    for (int o = 16; o > 0; o >>= 1)
        loss += __shfl_xor_sync(0xffffffffu, loss, o);

    int wid = tid >> 5;
    int lid = tid & 31;
    if (lid == 0) warp_sums[wid] = loss;
    __syncthreads();

    if (tid == 0) {
        float bsum = warp_sums[0] + warp_sums[1] + warp_sums[2] + warp_sums[3];
        unsigned long long pack = (1ull << 48) |
            (unsigned long long)__float2ull_rn(bsum * FIX_SCALE);   // bsum >= 0
        unsigned long long* bank = &g_bank[blockIdx.x & (NBANKS - 1)];
        // fire-and-forget: block retires without waiting on the L2 round-trip
        asm volatile("red.relaxed.gpu.global.add.u64 [%0], %1;"
                     :: "l"(bank), "l"(pack) : "memory");
    }

    // ---- finalizer: one warp of the LAST-launched block polls the banks ----
    if (blockIdx.x == NBLOCKS - 1 && tid < 32) {
        unsigned long long v;
        unsigned int ctot;
#pragma unroll 1
        do {
            asm volatile("ld.relaxed.gpu.global.u64 %0, [%1];"
                         : "=l"(v) : "l"(&g_bank[tid]));
            ctot = (unsigned int)(v >> 48);
#pragma unroll
            for (int o = 16; o > 0; o >>= 1)
                ctot += __shfl_xor_sync(0xffffffffu, ctot, o);
        } while (ctot != (unsigned int)NBLOCKS);

        // counts full => the v's we hold contain the complete sums
        unsigned long long s = v & SUM_MASK;
#pragma unroll
        for (int o = 16; o > 0; o >>= 1)
            s += __shfl_xor_sync(0xffffffffu, s, o);

        if (tid == 0)
            out[0] = (float)((double)s * (1.0 / (double)FIX_SCALE)
                             * (1.0 / (double)BATCH));
        // self-clean for the next graph replay (no REDs remain in flight)
        g_bank[tid] = 0ull;
    }
}

extern "C" void kernel_launch(void* const* d_in, const int* in_sizes, int n_in,
                              void* d_out, int out_size)
{
    const float* pred = (const float*)d_in[0];
    const float* targ = (const float*)d_in[1];
    float* out = (float*)d_out;
    (void)in_sizes; (void)n_in; (void)out_size;

    yolo_loss_kernel<<<NBLOCKS, THREADS>>>(pred, targ, out);
}